// round 8
// baseline (speedup 1.0000x reference)
#include <cuda_runtime.h>
#include <cuda_fp16.h>
#include <mma.h>
#include <math.h>
#include <stdint.h>

using namespace nvcuda;

// Problem constants
#define CHUNKS     8
#define CSIZE      512
#define DIM        4096
#define NROWS      16384
#define INV_TEMP   (1.0f / 0.15f)
#define SINK_ITERS 5

// Scratch (device globals — no runtime allocation allowed)
__device__ float  g_qlog[CHUNKS * CSIZE * CSIZE];      // 8 MB sinkhorn buffer / final Q fp32
__device__ float  g_p[64];                             // 8x8 chunk perm
__device__ __half g_eh[CHUNKS * CSIZE * CSIZE];        // 4 MB   Ê = 512*(Q - mu) fp16
__device__ float  g_mu[CHUNKS * CSIZE];                // row means of Q
__device__ __half g_yh[(size_t)NROWS * DIM];           // 128 MB Y fp16
__device__ float  g_s[(size_t)NROWS * CHUNKS];         // 512 KB row-chunk sums (fp32)

// ---------------------------------------------------------------------------
// Sinkhorn on 8x8 chunk logits
// ---------------------------------------------------------------------------
__global__ void sinkhorn_chunk_kernel(const float* __restrict__ logits,
                                      float* __restrict__ p_out) {
    __shared__ float s[64];
    int t = threadIdx.x;
    int r = t >> 3;
    int c = t & 7;
    float v = logits[t] * INV_TEMP;

    for (int it = 0; it < SINK_ITERS; ++it) {
        s[t] = v;
        __syncthreads();
        float mx = -1e30f;
        #pragma unroll
        for (int j = 0; j < 8; ++j) mx = fmaxf(mx, s[r * 8 + j]);
        float sm = 0.0f;
        #pragma unroll
        for (int j = 0; j < 8; ++j) sm += expf(s[r * 8 + j] - mx);
        v -= mx + logf(sm);
        __syncthreads();

        s[t] = v;
        __syncthreads();
        mx = -1e30f;
        #pragma unroll
        for (int j = 0; j < 8; ++j) mx = fmaxf(mx, s[j * 8 + c]);
        sm = 0.0f;
        #pragma unroll
        for (int j = 0; j < 8; ++j) sm += expf(s[j * 8 + c] - mx);
        v -= mx + logf(sm);
        __syncthreads();
    }
    p_out[t] = expf(v);
}

// ---------------------------------------------------------------------------
// Row LSE pass (over last axis). Block per row, 128 threads.
// ---------------------------------------------------------------------------
__global__ void lse_rows_kernel(const float* __restrict__ in,
                                float* __restrict__ out, float scale) {
    int row = blockIdx.x;
    const float* p = in  + (size_t)row * CSIZE;
    float*       q = out + (size_t)row * CSIZE;
    int t = threadIdx.x;

    float v[4];
    float mx = -1e30f;
    #pragma unroll
    for (int i = 0; i < 4; ++i) {
        v[i] = p[t + i * 128] * scale;
        mx = fmaxf(mx, v[i]);
    }

    __shared__ float red[128];
    red[t] = mx;
    __syncthreads();
    #pragma unroll
    for (int s2 = 64; s2 > 0; s2 >>= 1) {
        if (t < s2) red[t] = fmaxf(red[t], red[t + s2]);
        __syncthreads();
    }
    mx = red[0];
    __syncthreads();

    float sm = 0.0f;
    #pragma unroll
    for (int i = 0; i < 4; ++i) sm += expf(v[i] - mx);
    red[t] = sm;
    __syncthreads();
    #pragma unroll
    for (int s2 = 64; s2 > 0; s2 >>= 1) {
        if (t < s2) red[t] += red[t + s2];
        __syncthreads();
    }
    float lse = mx + logf(red[0]);

    #pragma unroll
    for (int i = 0; i < 4; ++i) q[t + i * 128] = v[i] - lse;
}

// ---------------------------------------------------------------------------
// Column LSE pass (over axis -2). Final pass writes exp(...) fp32 in place.
// ---------------------------------------------------------------------------
__global__ void lse_cols_kernel(float* __restrict__ buf, int apply_exp) {
    int chunk = blockIdx.x >> 4;
    int colbase = (blockIdx.x & 15) * 32;
    int t = threadIdx.x;
    int col = t & 31;
    int rg  = t >> 5;                 // 0..7
    float* base = buf + (size_t)chunk * CSIZE * CSIZE + colbase + col;

    __shared__ float red[8][32];

    float mx = -1e30f;
    for (int r = rg; r < CSIZE; r += 8) mx = fmaxf(mx, base[(size_t)r * CSIZE]);
    red[rg][col] = mx;
    __syncthreads();
    if (rg == 0) {
        float m = red[0][col];
        #pragma unroll
        for (int j = 1; j < 8; ++j) m = fmaxf(m, red[j][col]);
        red[0][col] = m;
    }
    __syncthreads();
    mx = red[0][col];
    __syncthreads();

    float sm = 0.0f;
    for (int r = rg; r < CSIZE; r += 8) sm += expf(base[(size_t)r * CSIZE] - mx);
    red[rg][col] = sm;
    __syncthreads();
    if (rg == 0) {
        float s = red[0][col];
        #pragma unroll
        for (int j = 1; j < 8; ++j) s += red[j][col];
        red[0][col] = s;
    }
    __syncthreads();
    float lse = mx + logf(red[0][col]);

    if (apply_exp) {
        for (int r = rg; r < CSIZE; r += 8)
            base[(size_t)r * CSIZE] = expf(base[(size_t)r * CSIZE] - lse);
    } else {
        for (int r = rg; r < CSIZE; r += 8)
            base[(size_t)r * CSIZE] -= lse;
    }
}

// ---------------------------------------------------------------------------
// Build mu (per Q row mean) and Ê = 512*(Q - mu) in fp16. Block per row.
// ---------------------------------------------------------------------------
__global__ void emu_kernel(const float* __restrict__ q,
                           __half* __restrict__ eh,
                           float* __restrict__ mu) {
    int row = blockIdx.x;             // 0 .. 4095 (chunk*512 + n)
    const float* p = q + (size_t)row * CSIZE;
    __half* e = eh + (size_t)row * CSIZE;
    int t = threadIdx.x;              // 128

    float v[4];
    float sm = 0.0f;
    #pragma unroll
    for (int i = 0; i < 4; ++i) {
        v[i] = p[t + i * 128];
        sm += v[i];
    }
    __shared__ float red[128];
    red[t] = sm;
    __syncthreads();
    #pragma unroll
    for (int s2 = 64; s2 > 0; s2 >>= 1) {
        if (t < s2) red[t] += red[t + s2];
        __syncthreads();
    }
    float m = red[0] * (1.0f / CSIZE);
    if (t == 0) mu[row] = m;

    #pragma unroll
    for (int i = 0; i < 4; ++i)
        e[t + i * 128] = __float2half((v[i] - m) * 512.0f);
}

// ---------------------------------------------------------------------------
// Chunk mix -> fp16 Y, plus fp32 row-chunk sums S[m*8+c].
// Block = 256 threads = 2 rows x 128 lanes.
// ---------------------------------------------------------------------------
__global__ void mix_half_kernel(const float* __restrict__ x,
                                __half* __restrict__ yh,
                                float* __restrict__ S,
                                const float* __restrict__ P) {
    __shared__ float p[64];
    __shared__ float ws[8][8];        // [warp][chunk]
    if (threadIdx.x < 64) p[threadIdx.x] = P[threadIdx.x];
    __syncthreads();

    int idx = blockIdx.x * blockDim.x + threadIdx.x;
    int b  = idx >> 7;
    int d4 = idx & 127;
    int warp = threadIdx.x >> 5;
    int lane = threadIdx.x & 31;

    const float4* xb = (const float4*)(x + (size_t)b * DIM) + d4;

    float4 xv[8];
    #pragma unroll
    for (int j = 0; j < 8; ++j) xv[j] = xb[(size_t)j * 128];

    float srow[8];
    #pragma unroll
    for (int i = 0; i < 8; ++i) {
        float4 acc = make_float4(0.f, 0.f, 0.f, 0.f);
        #pragma unroll
        for (int j = 0; j < 8; ++j) {
            float w = p[i * 8 + j];
            acc.x += w * xv[j].x;
            acc.y += w * xv[j].y;
            acc.z += w * xv[j].z;
            acc.w += w * xv[j].w;
        }
        srow[i] = acc.x + acc.y + acc.z + acc.w;
        __half2 h01 = __floats2half2_rn(acc.x, acc.y);
        __half2 h23 = __floats2half2_rn(acc.z, acc.w);
        size_t e = (size_t)b * DIM + (size_t)i * CSIZE + (size_t)d4 * 4;
        ((__half2*)yh)[e >> 1]       = h01;
        ((__half2*)yh)[(e >> 1) + 1] = h23;
    }

    // reduce srow over the 128 lanes of this row (4 warps)
    #pragma unroll
    for (int i = 0; i < 8; ++i) {
        float v = srow[i];
        #pragma unroll
        for (int off = 16; off > 0; off >>= 1)
            v += __shfl_down_sync(0xFFFFFFFFu, v, off);
        if (lane == 0) ws[warp][i] = v;
    }
    __syncthreads();
    if (threadIdx.x < 16) {
        int rsel  = threadIdx.x >> 3;     // 0/1: which row in block
        int chunk = threadIdx.x & 7;
        float v = ws[rsel * 4 + 0][chunk] + ws[rsel * 4 + 1][chunk]
                + ws[rsel * 4 + 2][chunk] + ws[rsel * 4 + 3][chunk];
        int brow = blockIdx.x * 2 + rsel;
        S[(size_t)brow * 8 + chunk] = v;
    }
}

// ---------------------------------------------------------------------------
// WMMA GEMM with fp16 accumulators: Z = Y @ Ê^T, then
// out = Z/512 + mu_n * S[m,c] in the epilogue.
// CTA 128x128, K-step 32, 2-stage cp.async, 256 threads (8 warps, 64x32 warp tile)
// Epilogue scratch ld = 40 halfs (80 B, multiple of 16 B — WMMA store contract).
// ---------------------------------------------------------------------------
#define LDS_PAD 40
#define NKITER  16
#define EPI_LD  40          // 64x40 per warp: 8 * 2560 halfs = 40960 B = sA+sB

__device__ __forceinline__ void cp16(uint32_t dst, const void* src) {
    asm volatile("cp.async.cg.shared.global [%0], [%1], 16;" :: "r"(dst), "l"(src));
}

__global__ __launch_bounds__(256, 2)
void wmma_gemm_kernel(const __half* __restrict__ yh,
                      const __half* __restrict__ eh,
                      const float* __restrict__ mu,
                      const float* __restrict__ S,
                      float* __restrict__ out) {
    __shared__ __align__(32) __half sA[2][128 * LDS_PAD];
    __shared__ __align__(32) __half sB[2][128 * LDS_PAD];

    const int c  = blockIdx.z;
    const int m0 = blockIdx.y * 128;
    const int n0 = blockIdx.x * 128;
    const int tid = threadIdx.x;
    const int wid = tid >> 5;
    const int lane = tid & 31;
    const int wm  = wid & 1;       // 0..1 -> 64-row slab
    const int wn  = wid >> 1;      // 0..3 -> 32-col slab

    wmma::fragment<wmma::accumulator, 16, 16, 16, __half> acc[4][2];
    #pragma unroll
    for (int i = 0; i < 4; ++i)
        #pragma unroll
        for (int j = 0; j < 2; ++j) wmma::fill_fragment(acc[i][j], __float2half(0.0f));

    const int r0  = (tid + 0)   >> 2;
    const int cb0 = (tid + 0)   & 3;
    const int r1  = (tid + 256) >> 2;
    const int cb1 = (tid + 256) & 3;

    uint32_t sA0[2], sA1[2], sB0[2], sB1[2];
    #pragma unroll
    for (int b = 0; b < 2; ++b) {
        sA0[b] = (uint32_t)__cvta_generic_to_shared(&sA[b][r0 * LDS_PAD + cb0 * 8]);
        sA1[b] = (uint32_t)__cvta_generic_to_shared(&sA[b][r1 * LDS_PAD + cb1 * 8]);
        sB0[b] = (uint32_t)__cvta_generic_to_shared(&sB[b][r0 * LDS_PAD + cb0 * 8]);
        sB1[b] = (uint32_t)__cvta_generic_to_shared(&sB[b][r1 * LDS_PAD + cb1 * 8]);
    }

    const __half* Abase = yh + (size_t)m0 * DIM + (size_t)c * CSIZE;
    const __half* Bbase = eh + (size_t)c * CSIZE * CSIZE + (size_t)n0 * CSIZE;

    auto issue_loads = [&](int i, int buf) {
        int kk = i << 5;
        const __half* A = Abase + kk;
        const __half* B = Bbase + kk;
        cp16(sA0[buf], A + (size_t)r0 * DIM + cb0 * 8);
        cp16(sA1[buf], A + (size_t)r1 * DIM + cb1 * 8);
        cp16(sB0[buf], B + (size_t)r0 * CSIZE + cb0 * 8);
        cp16(sB1[buf], B + (size_t)r1 * CSIZE + cb1 * 8);
        asm volatile("cp.async.commit_group;" ::: "memory");
    };

    issue_loads(0, 0);

    for (int i = 0; i < NKITER; ++i) {
        int s = i & 1;
        asm volatile("cp.async.wait_group 0;" ::: "memory");
        __syncthreads();

        if (i < NKITER - 1) issue_loads(i + 1, s ^ 1);

        #pragma unroll
        for (int k2 = 0; k2 < 2; ++k2) {
            wmma::fragment<wmma::matrix_a, 16, 16, 16, __half, wmma::row_major> af[4];
            wmma::fragment<wmma::matrix_b, 16, 16, 16, __half, wmma::col_major> bf[2];
            #pragma unroll
            for (int mi = 0; mi < 4; ++mi)
                wmma::load_matrix_sync(af[mi],
                    &sA[s][(wm * 64 + mi * 16) * LDS_PAD + k2 * 16], LDS_PAD);
            #pragma unroll
            for (int nj = 0; nj < 2; ++nj)
                wmma::load_matrix_sync(bf[nj],
                    &sB[s][(wn * 32 + nj * 16) * LDS_PAD + k2 * 16], LDS_PAD);
            #pragma unroll
            for (int mi = 0; mi < 4; ++mi)
                #pragma unroll
                for (int nj = 0; nj < 2; ++nj)
                    wmma::mma_sync(acc[mi][nj], af[mi], bf[nj], acc[mi][nj]);
        }
        __syncthreads();
    }

    // Epilogue: roundtrip through smem (reuse sA/sB), add rank-1 correction.
    __syncthreads();
    __half* scratch = &sA[0][0] + wid * (64 * EPI_LD);
    #pragma unroll
    for (int mi = 0; mi < 4; ++mi)
        #pragma unroll
        for (int nj = 0; nj < 2; ++nj)
            wmma::store_matrix_sync(scratch + (mi * 16) * EPI_LD + nj * 16,
                                    acc[mi][nj], EPI_LD, wmma::mem_row_major);
    __syncwarp();

    const int ncol = n0 + wn * 32 + lane;
    const float mun = mu[c * CSIZE + ncol];
    const float* Sbase = S + (size_t)(m0 + wm * 64) * 8 + c;
    float* obase = out + (size_t)(m0 + wm * 64) * DIM + (size_t)c * CSIZE + ncol;

    #pragma unroll 4
    for (int r = 0; r < 64; ++r) {
        float z = __half2float(scratch[r * EPI_LD + lane]);
        float sv = Sbase[(size_t)r * 8];
        obase[(size_t)r * DIM] = z * (1.0f / 512.0f) + mun * sv;
    }
}

// ---------------------------------------------------------------------------
// Launch
// ---------------------------------------------------------------------------
extern "C" void kernel_launch(void* const* d_in, const int* in_sizes, int n_in,
                              void* d_out, int out_size) {
    const float* x            = (const float*)d_in[0];
    const float* chunk_logits = (const float*)d_in[1];
    const float* intra_logits = (const float*)d_in[2];
    float*       out          = (float*)d_out;

    float*  qlog; cudaGetSymbolAddress((void**)&qlog, g_qlog);
    float*  p;    cudaGetSymbolAddress((void**)&p,    g_p);
    __half* eh;   cudaGetSymbolAddress((void**)&eh,   g_eh);
    float*  mu;   cudaGetSymbolAddress((void**)&mu,   g_mu);
    __half* yh;   cudaGetSymbolAddress((void**)&yh,   g_yh);
    float*  S;    cudaGetSymbolAddress((void**)&S,    g_s);

    // 1) 8x8 chunk sinkhorn
    sinkhorn_chunk_kernel<<<1, 64>>>(chunk_logits, p);

    // 2) intra sinkhorn (5x row+col); exp fused into final col pass (fp32)
    lse_rows_kernel<<<CHUNKS * CSIZE, 128>>>(intra_logits, qlog, INV_TEMP);
    lse_cols_kernel<<<CHUNKS * 16, 256>>>(qlog, 0);
    for (int it = 1; it < SINK_ITERS; ++it) {
        lse_rows_kernel<<<CHUNKS * CSIZE, 128>>>(qlog, qlog, 1.0f);
        lse_cols_kernel<<<CHUNKS * 16, 256>>>(qlog, (it == SINK_ITERS - 1) ? 1 : 0);
    }

    // 3) mu + Ê
    emu_kernel<<<CHUNKS * CSIZE, 128>>>(qlog, eh, mu);

    // 4) chunk mix -> fp16 Y + fp32 S
    mix_half_kernel<<<(NROWS * 128) / 256, 256>>>(x, yh, S, p);

    // 5) fp16-accum GEMM + rank-1 epilogue
    dim3 grid(4, NROWS / 128, CHUNKS);
    wmma_gemm_kernel<<<grid, 256>>>(yh, eh, mu, S, out);
}

// round 9
// speedup vs baseline: 1.2176x; 1.2176x over previous
#include <cuda_runtime.h>
#include <cuda_fp16.h>
#include <mma.h>
#include <math.h>
#include <stdint.h>

using namespace nvcuda;

// Problem constants
#define CHUNKS     8
#define CSIZE      512
#define DIM        4096
#define NROWS      16384
#define INV_TEMP   (1.0f / 0.15f)
#define SINK_ITERS 5

// Scratch (device globals — no runtime allocation allowed)
__device__ float  g_qlog[CHUNKS * CSIZE * CSIZE];      // 8 MB sinkhorn buffer
__device__ float  g_p[64];                             // 8x8 chunk perm
__device__ __half g_qh[CHUNKS * CSIZE * CSIZE];        // 4 MB   Q fp16
__device__ __half g_yh[(size_t)NROWS * DIM];           // 128 MB Y fp16

// ---------------------------------------------------------------------------
// Sinkhorn on 8x8 chunk logits
// ---------------------------------------------------------------------------
__global__ void sinkhorn_chunk_kernel(const float* __restrict__ logits,
                                      float* __restrict__ p_out) {
    __shared__ float s[64];
    int t = threadIdx.x;
    int r = t >> 3;
    int c = t & 7;
    float v = logits[t] * INV_TEMP;

    for (int it = 0; it < SINK_ITERS; ++it) {
        s[t] = v;
        __syncthreads();
        float mx = -1e30f;
        #pragma unroll
        for (int j = 0; j < 8; ++j) mx = fmaxf(mx, s[r * 8 + j]);
        float sm = 0.0f;
        #pragma unroll
        for (int j = 0; j < 8; ++j) sm += expf(s[r * 8 + j] - mx);
        v -= mx + logf(sm);
        __syncthreads();

        s[t] = v;
        __syncthreads();
        mx = -1e30f;
        #pragma unroll
        for (int j = 0; j < 8; ++j) mx = fmaxf(mx, s[j * 8 + c]);
        sm = 0.0f;
        #pragma unroll
        for (int j = 0; j < 8; ++j) sm += expf(s[j * 8 + c] - mx);
        v -= mx + logf(sm);
        __syncthreads();
    }
    p_out[t] = expf(v);
}

// ---------------------------------------------------------------------------
// Row LSE pass (over last axis). Warp per row, float4 loads, shuffle
// reductions only — no __syncthreads. Grid = 1024 blocks x 128 threads.
// ---------------------------------------------------------------------------
__global__ void lse_rows_kernel(const float* __restrict__ in,
                                float* __restrict__ out, float scale) {
    int row  = blockIdx.x * 4 + (threadIdx.x >> 5);
    int lane = threadIdx.x & 31;
    const float4* p = (const float4*)(in  + (size_t)row * CSIZE);
    float4*       q = (float4*)(out + (size_t)row * CSIZE);

    float4 v[4];
    float mx = -1e30f;
    #pragma unroll
    for (int i = 0; i < 4; ++i) {
        float4 t = p[lane + i * 32];
        t.x *= scale; t.y *= scale; t.z *= scale; t.w *= scale;
        v[i] = t;
        mx = fmaxf(mx, fmaxf(fmaxf(t.x, t.y), fmaxf(t.z, t.w)));
    }
    #pragma unroll
    for (int off = 16; off > 0; off >>= 1)
        mx = fmaxf(mx, __shfl_xor_sync(0xFFFFFFFFu, mx, off));

    float sm = 0.0f;
    #pragma unroll
    for (int i = 0; i < 4; ++i) {
        sm += expf(v[i].x - mx) + expf(v[i].y - mx)
            + expf(v[i].z - mx) + expf(v[i].w - mx);
    }
    #pragma unroll
    for (int off = 16; off > 0; off >>= 1)
        sm += __shfl_xor_sync(0xFFFFFFFFu, sm, off);

    float lse = mx + logf(sm);

    #pragma unroll
    for (int i = 0; i < 4; ++i) {
        float4 t = v[i];
        t.x -= lse; t.y -= lse; t.z -= lse; t.w -= lse;
        q[lane + i * 32] = t;
    }
}

// ---------------------------------------------------------------------------
// Column LSE pass (over axis -2). Grid = 8 chunks * 16 colgroups, 512 thr
// (16 row-groups x 32 cols). Final pass writes exp(q - lse) as fp16 into qh.
// ---------------------------------------------------------------------------
__global__ void lse_cols_kernel(float* __restrict__ buf,
                                __half* __restrict__ qh, int apply_exp) {
    int chunk = blockIdx.x >> 4;
    int colbase = (blockIdx.x & 15) * 32;
    int t = threadIdx.x;
    int col = t & 31;
    int rg  = t >> 5;                 // 0..15
    size_t base_i = (size_t)chunk * CSIZE * CSIZE + colbase + col;
    float* base = buf + base_i;

    __shared__ float red[16][32];

    float mx = -1e30f;
    for (int r = rg; r < CSIZE; r += 16) mx = fmaxf(mx, base[(size_t)r * CSIZE]);
    red[rg][col] = mx;
    __syncthreads();
    if (rg == 0) {
        float m = red[0][col];
        #pragma unroll
        for (int j = 1; j < 16; ++j) m = fmaxf(m, red[j][col]);
        red[0][col] = m;
    }
    __syncthreads();
    mx = red[0][col];
    __syncthreads();

    float sm = 0.0f;
    for (int r = rg; r < CSIZE; r += 16) sm += expf(base[(size_t)r * CSIZE] - mx);
    red[rg][col] = sm;
    __syncthreads();
    if (rg == 0) {
        float s = red[0][col];
        #pragma unroll
        for (int j = 1; j < 16; ++j) s += red[j][col];
        red[0][col] = s;
    }
    __syncthreads();
    float lse = mx + logf(red[0][col]);

    if (apply_exp) {
        __half* qbase = qh + base_i;
        for (int r = rg; r < CSIZE; r += 16)
            qbase[(size_t)r * CSIZE] =
                __float2half(expf(base[(size_t)r * CSIZE] - lse));
    } else {
        for (int r = rg; r < CSIZE; r += 16)
            base[(size_t)r * CSIZE] -= lse;
    }
}

// ---------------------------------------------------------------------------
// Chunk mix producing fp16: y = P @ x per (b, d)
// ---------------------------------------------------------------------------
__global__ void mix_half_kernel(const float* __restrict__ x,
                                __half* __restrict__ yh,
                                const float* __restrict__ P) {
    __shared__ float p[64];
    if (threadIdx.x < 64) p[threadIdx.x] = P[threadIdx.x];
    __syncthreads();

    int idx = blockIdx.x * blockDim.x + threadIdx.x;
    int b  = idx >> 7;
    int d4 = idx & 127;

    const float4* xb = (const float4*)(x + (size_t)b * DIM) + d4;

    float4 xv[8];
    #pragma unroll
    for (int j = 0; j < 8; ++j) xv[j] = xb[(size_t)j * 128];

    #pragma unroll
    for (int i = 0; i < 8; ++i) {
        float4 acc = make_float4(0.f, 0.f, 0.f, 0.f);
        #pragma unroll
        for (int j = 0; j < 8; ++j) {
            float w = p[i * 8 + j];
            acc.x += w * xv[j].x;
            acc.y += w * xv[j].y;
            acc.z += w * xv[j].z;
            acc.w += w * xv[j].w;
        }
        __half2 h01 = __floats2half2_rn(acc.x, acc.y);
        __half2 h23 = __floats2half2_rn(acc.z, acc.w);
        size_t e = (size_t)b * DIM + (size_t)i * CSIZE + (size_t)d4 * 4;  // even
        ((__half2*)yh)[e >> 1]       = h01;
        ((__half2*)yh)[(e >> 1) + 1] = h23;
    }
}

// ---------------------------------------------------------------------------
// WMMA (HMMA) GEMM, fp16 in / fp32 accum: per CTA 128x128 tile, K = 512.
// Double-buffered cp.async, 8 warps (2M x 4N), warp tile 64x32.
// (Round-5 config — measured at the legacy-HMMA issue ceiling.)
// ---------------------------------------------------------------------------
#define LDS_PAD 40          // padded row stride (elems): 80 B, multiple of 16 B
#define NKITER  16          // 512 / 32

__device__ __forceinline__ void cp16(uint32_t dst, const void* src) {
    asm volatile("cp.async.cg.shared.global [%0], [%1], 16;" :: "r"(dst), "l"(src));
}

__global__ __launch_bounds__(256, 2)
void wmma_gemm_kernel(const __half* __restrict__ yh,
                      const __half* __restrict__ qh,
                      float* __restrict__ out) {
    __shared__ __half sA[2][128 * LDS_PAD];
    __shared__ __half sB[2][128 * LDS_PAD];

    const int c  = blockIdx.z;
    const int m0 = blockIdx.y * 128;
    const int n0 = blockIdx.x * 128;
    const int tid = threadIdx.x;
    const int wid = tid >> 5;
    const int wm  = wid & 1;       // 0..1  -> 64-row slab
    const int wn  = wid >> 1;      // 0..3  -> 32-col slab

    wmma::fragment<wmma::accumulator, 16, 16, 16, float> acc[4][2];
    #pragma unroll
    for (int i = 0; i < 4; ++i)
        #pragma unroll
        for (int j = 0; j < 2; ++j) wmma::fill_fragment(acc[i][j], 0.0f);

    // per-thread load assignment: 512 x 16B chunks per tile, 2 per thread
    const int r0  = (tid + 0)   >> 2;
    const int cb0 = (tid + 0)   & 3;
    const int r1  = (tid + 256) >> 2;
    const int cb1 = (tid + 256) & 3;

    uint32_t sA0[2], sA1[2], sB0[2], sB1[2];
    #pragma unroll
    for (int b = 0; b < 2; ++b) {
        sA0[b] = (uint32_t)__cvta_generic_to_shared(&sA[b][r0 * LDS_PAD + cb0 * 8]);
        sA1[b] = (uint32_t)__cvta_generic_to_shared(&sA[b][r1 * LDS_PAD + cb1 * 8]);
        sB0[b] = (uint32_t)__cvta_generic_to_shared(&sB[b][r0 * LDS_PAD + cb0 * 8]);
        sB1[b] = (uint32_t)__cvta_generic_to_shared(&sB[b][r1 * LDS_PAD + cb1 * 8]);
    }

    const __half* Abase = yh + (size_t)m0 * DIM + (size_t)c * CSIZE;
    const __half* Bbase = qh + (size_t)c * CSIZE * CSIZE + (size_t)n0 * CSIZE;

    auto issue_loads = [&](int i, int buf) {
        int kk = i << 5;
        const __half* A = Abase + kk;
        const __half* B = Bbase + kk;
        cp16(sA0[buf], A + (size_t)r0 * DIM + cb0 * 8);
        cp16(sA1[buf], A + (size_t)r1 * DIM + cb1 * 8);
        cp16(sB0[buf], B + (size_t)r0 * CSIZE + cb0 * 8);
        cp16(sB1[buf], B + (size_t)r1 * CSIZE + cb1 * 8);
        asm volatile("cp.async.commit_group;" ::: "memory");
    };

    issue_loads(0, 0);

    for (int i = 0; i < NKITER; ++i) {
        int s = i & 1;
        asm volatile("cp.async.wait_group 0;" ::: "memory");
        __syncthreads();

        if (i < NKITER - 1) issue_loads(i + 1, s ^ 1);

        #pragma unroll
        for (int k2 = 0; k2 < 2; ++k2) {
            wmma::fragment<wmma::matrix_a, 16, 16, 16, __half, wmma::row_major> af[4];
            wmma::fragment<wmma::matrix_b, 16, 16, 16, __half, wmma::col_major> bf[2];
            #pragma unroll
            for (int mi = 0; mi < 4; ++mi)
                wmma::load_matrix_sync(af[mi],
                    &sA[s][(wm * 64 + mi * 16) * LDS_PAD + k2 * 16], LDS_PAD);
            #pragma unroll
            for (int nj = 0; nj < 2; ++nj)
                wmma::load_matrix_sync(bf[nj],
                    &sB[s][(wn * 32 + nj * 16) * LDS_PAD + k2 * 16], LDS_PAD);
            #pragma unroll
            for (int mi = 0; mi < 4; ++mi)
                #pragma unroll
                for (int nj = 0; nj < 2; ++nj)
                    wmma::mma_sync(acc[mi][nj], af[mi], bf[nj], acc[mi][nj]);
        }
        __syncthreads();
    }

    // epilogue: direct store to out
    #pragma unroll
    for (int mi = 0; mi < 4; ++mi) {
        #pragma unroll
        for (int nj = 0; nj < 2; ++nj) {
            float* dst = out + (size_t)(m0 + wm * 64 + mi * 16) * DIM
                             + (size_t)c * CSIZE + n0 + wn * 32 + nj * 16;
            wmma::store_matrix_sync(dst, acc[mi][nj], DIM, wmma::mem_row_major);
        }
    }
}

// ---------------------------------------------------------------------------
// Launch
// ---------------------------------------------------------------------------
extern "C" void kernel_launch(void* const* d_in, const int* in_sizes, int n_in,
                              void* d_out, int out_size) {
    const float* x            = (const float*)d_in[0];
    const float* chunk_logits = (const float*)d_in[1];
    const float* intra_logits = (const float*)d_in[2];
    float*       out          = (float*)d_out;

    float*  qlog; cudaGetSymbolAddress((void**)&qlog, g_qlog);
    float*  p;    cudaGetSymbolAddress((void**)&p,    g_p);
    __half* qh;   cudaGetSymbolAddress((void**)&qh,   g_qh);
    __half* yh;   cudaGetSymbolAddress((void**)&yh,   g_yh);

    // 1) 8x8 chunk sinkhorn
    sinkhorn_chunk_kernel<<<1, 64>>>(chunk_logits, p);

    // 2) intra sinkhorn (5x row+col); exp + fp16 cast fused into final col pass
    lse_rows_kernel<<<CHUNKS * CSIZE / 4, 128>>>(intra_logits, qlog, INV_TEMP);
    lse_cols_kernel<<<CHUNKS * 16, 512>>>(qlog, qh, 0);
    for (int it = 1; it < SINK_ITERS; ++it) {
        lse_rows_kernel<<<CHUNKS * CSIZE / 4, 128>>>(qlog, qlog, 1.0f);
        lse_cols_kernel<<<CHUNKS * 16, 512>>>(qlog, qh, (it == SINK_ITERS - 1) ? 1 : 0);
    }

    // 3) chunk mix -> fp16 Y
    mix_half_kernel<<<(NROWS * 128) / 256, 256>>>(x, yh, p);

    // 4) tensor-core GEMM (fp16 in, fp32 accum): out = Y Q^T per chunk
    dim3 grid(4, NROWS / 128, CHUNKS);
    wmma_gemm_kernel<<<grid, 256>>>(yh, qh, out);
}